// round 3
// baseline (speedup 1.0000x reference)
#include <cuda_runtime.h>
#include <math.h>

#define NUM_FIELDS 32
#define FIELD_DIM  50000
#define EMB_DIM    64
#define ATT_DIM    32
#define NPAIRS     496
#define ET_STRIDE  33   // padded stride: bank = (d + f) % 32 -> conflict-free / broadcast

typedef unsigned long long ull;

// ---- packed f32x2 helpers (PTX-only; ptxas never auto-fuses to FFMA2) ----
__device__ __forceinline__ ull pk2(float lo, float hi){
    ull r; asm("mov.b64 %0, {%1, %2};" : "=l"(r) : "f"(lo), "f"(hi)); return r;
}
__device__ __forceinline__ void upk2(ull v, float &lo, float &hi){
    asm("mov.b64 {%0, %1}, %2;" : "=f"(lo), "=f"(hi) : "l"(v));
}
__device__ __forceinline__ void fma2(ull &d, ull a, ull b){
    asm("fma.rn.f32x2 %0, %1, %2, %0;" : "+l"(d) : "l"(a), "l"(b));
}

__global__ __launch_bounds__(256, 2)
void afm_kernel(const int*   __restrict__ x,
                const float* __restrict__ emb,
                const float* __restrict__ lin,
                const float* __restrict__ lin_bias,
                const float* __restrict__ W1,
                const float* __restrict__ b1,
                const float* __restrict__ w2,
                const float* __restrict__ pw,
                float*       __restrict__ out)
{
    __shared__ float sEt[EMB_DIM * ET_STRIDE];          // transposed embeddings Et[d][f]
    __shared__ __align__(16) float sW1[EMB_DIM * ATT_DIM]; // row-major [d][a]
    __shared__ float sB1[ATT_DIM], sW2[ATT_DIM], sPW[EMB_DIM];
    __shared__ float sS[512], sQ[512];
    __shared__ float sRed[256], sRedB[256];
    __shared__ float sFirst;

    const int t = threadIdx.x;
    const int b = blockIdx.x;

    // ---- gather embeddings -> transposed SMEM (conflict-free scatter) ----
    {
        int f = t >> 3, k = t & 7;
        int id = x[b * NUM_FIELDS + f] + f * FIELD_DIM;
        const float4* src = (const float4*)(emb + (size_t)id * EMB_DIM + k * 8);
        float4 v0 = src[0], v1 = src[1];
        int d0 = k * 8;
        sEt[(d0+0)*ET_STRIDE+f] = v0.x; sEt[(d0+1)*ET_STRIDE+f] = v0.y;
        sEt[(d0+2)*ET_STRIDE+f] = v0.z; sEt[(d0+3)*ET_STRIDE+f] = v0.w;
        sEt[(d0+4)*ET_STRIDE+f] = v1.x; sEt[(d0+5)*ET_STRIDE+f] = v1.y;
        sEt[(d0+6)*ET_STRIDE+f] = v1.z; sEt[(d0+7)*ET_STRIDE+f] = v1.w;
    }
    // ---- stage small weights ----
    {
        const float4* g = (const float4*)W1;
        float4* s4 = (float4*)sW1;
        s4[t]       = g[t];
        s4[t + 256] = g[t + 256];
    }
    if (t < 32) { sB1[t] = b1[t]; sW2[t] = w2[t]; }
    if (t < 64) sPW[t] = pw[t];
    if (t >= 240) { sS[t + 256] = -1e30f; sQ[t + 256] = 0.f; }   // pad slots 496..511

    // ---- first-order linear term (warp 0) ----
    if (t < 32) {
        int id = x[b * NUM_FIELDS + t] + t * FIELD_DIM;
        float v = lin[id];
        #pragma unroll
        for (int off = 16; off; off >>= 1) v += __shfl_down_sync(0xffffffffu, v, off);
        if (t == 0) sFirst = v + lin_bias[0];
    }
    __syncthreads();

    // ---- decode pair indices (triu order, row-major i<j) ----
    const int pA = t;
    const int pB = t + 256;
    const bool hasB = (pB < NPAIRS);
    int ia, ja, ib, jb;
    {
        int p = pA, i = 0, c = 31;
        while (p >= c) { p -= c; c--; i++; }
        ia = i; ja = i + 1 + p;
    }
    if (hasB) {
        int p = pB, i = 0, c = 31;
        while (p >= c) { p -= c; c--; i++; }
        ib = i; jb = i + 1 + p;
    } else { ib = 0; jb = 1; }

    // ---- per-pair bilinear forms: h[a] = sum_d e_i*e_j*W1[d][a], q = sum_d e_i*e_j*pw[d]
    ull h0[16], h1[16];
    #pragma unroll
    for (int k = 0; k < 16; k++) { h0[k] = 0ull; h1[k] = 0ull; }
    float q0 = 0.f, q1 = 0.f;

    const float* pe  = sEt;
    const ull*   pwr = (const ull*)sW1;   // pairs (a=2k, a=2k+1)
    const float* ppw = sPW;
    #pragma unroll 2
    for (int d = 0; d < EMB_DIM; d++) {
        float pa = pe[ia] * pe[ja];       // bank (d+i)%32: distinct-i -> distinct banks, same-i -> broadcast
        float pb = pe[ib] * pe[jb];
        float pwd = *ppw;
        q0 = fmaf(pa, pwd, q0);
        q1 = fmaf(pb, pwd, q1);
        ull pa2 = pk2(pa, pa), pb2 = pk2(pb, pb);
        #pragma unroll
        for (int k = 0; k < 16; k++) {
            ull wk = pwr[k];              // 64-bit broadcast load
            fma2(h0[k], wk, pa2);
            fma2(h1[k], wk, pb2);
        }
        pe += ET_STRIDE; pwr += 16; ppw++;
    }

    // ---- attention MLP head: s = sum_a w2[a]*relu(h[a]+b1[a]) ----
    float s0 = 0.f, s1 = 0.f;
    #pragma unroll
    for (int k = 0; k < 16; k++) {
        float lo, hi;
        upk2(h0[k], lo, hi);
        s0 += sW2[2*k]   * fmaxf(lo + sB1[2*k],   0.f)
            + sW2[2*k+1] * fmaxf(hi + sB1[2*k+1], 0.f);
        upk2(h1[k], lo, hi);
        s1 += sW2[2*k]   * fmaxf(lo + sB1[2*k],   0.f)
            + sW2[2*k+1] * fmaxf(hi + sB1[2*k+1], 0.f);
    }
    sS[pA] = s0; sQ[pA] = q0;
    if (hasB) { sS[pB] = s1; sQ[pB] = q1; }
    __syncthreads();

    // ---- softmax over 496 pairs + weighted sum of q (block reductions) ----
    float m = fmaxf(sS[t], sS[t + 256]);
    sRed[t] = m; __syncthreads();
    #pragma unroll
    for (int off = 128; off > 0; off >>= 1) {
        if (t < off) sRed[t] = fmaxf(sRed[t], sRed[t + off]);
        __syncthreads();
    }
    float mx = sRed[0];
    __syncthreads();

    float e0 = expf(sS[t] - mx);
    float e1 = (t < 240) ? expf(sS[t + 256] - mx) : 0.f;
    sRed[t]  = e0 + e1;
    sRedB[t] = e0 * sQ[t] + e1 * sQ[t + 256];
    __syncthreads();
    #pragma unroll
    for (int off = 128; off > 0; off >>= 1) {
        if (t < off) { sRed[t] += sRed[t + off]; sRedB[t] += sRedB[t + off]; }
        __syncthreads();
    }

    if (t == 0) {
        float second = sRedB[0] / sRed[0];   // sum(attn * q)
        float y = sFirst + second;
        out[b] = 1.f / (1.f + expf(-y));
    }
}

extern "C" void kernel_launch(void* const* d_in, const int* in_sizes, int n_in,
                              void* d_out, int out_size)
{
    const int*   x   = (const int*)  d_in[0];
    const float* emb = (const float*)d_in[1];
    const float* lin = (const float*)d_in[2];
    const float* lb  = (const float*)d_in[3];
    const float* W1  = (const float*)d_in[4];
    const float* b1  = (const float*)d_in[5];
    const float* w2  = (const float*)d_in[6];
    const float* pwv = (const float*)d_in[7];
    const int B = in_sizes[0] / NUM_FIELDS;
    afm_kernel<<<B, 256>>>(x, emb, lin, lb, W1, b1, w2, pwv, (float*)d_out);
}